// round 16
// baseline (speedup 1.0000x reference)
#include <cuda_runtime.h>
#include <cuda_fp16.h>
#include <cstdint>

// Problem constants
#define BB   32
#define TT   2048
#define FF   512
#define UU   128
#define MM   (BB * TT)
#define NEG_BIG -1.0e9f
#define CAP  128               // candidate cap per row
#define BAND 4.0e-3f           // approx-score safety band

// approx score kernel tiling
#define MBLK 128
#define KC   32
#define NC   (FF / KC)         // 16
#define NTH  512               // 16 warps: 4 m x 4 n
#define NBLK (MM / MBLK)       // 512

#define ROWB  80
#define ATILE (128 * ROWB)     // 10240
#define SM_A(b)  ((b) * ATILE)
#define SM_B(b)  (20480 + (b) * ATILE)
#define SM_FLAGS 40960
#define SM_PART  41472
#define SM_W2    43520
#define SM_B1    44032
#define SM_TOTAL 44544

// rescore kernel smem (16-frame tiles, 2-stage cp.async B pipeline)
#define R_ROWA  1040                       // 512 halves + pad
#define R_ROWB  144                        // 64 halves + pad
#define R_AHI   0
#define R_ALO   (16 * R_ROWA)              // 16640
#define R_BSTG  18432                      // 128 rows x 144 B per split-stage
#define R_B(s,h) (33280 + ((s) * 2 + (h)) * R_BSTG)   // 33280 .. 107008
#define R_FLAGS 107008                     // 16 int
#define R_PART  (R_FLAGS + 64)             // 16 x 8 float
#define R_W2    (R_PART + 512)
#define R_B1    (R_W2 + 512)
#define R_TOTAL (R_B1 + 512)               // 108608 -> 2 blocks/SM

// Static scratch
__device__ float          g_scores[MM];
__device__ unsigned char  g_sel[MM];
__device__ __half         g_Whi[UU * FF];
__device__ __half         g_Wlo[UU * FF];
__device__ int            g_cand[BB * CAP];
__device__ float          g_exact[BB * CAP];

// ---------------- PTX helpers ----------------
__device__ __forceinline__ uint32_t smem_u32(const void* p) {
    uint32_t a;
    asm("{ .reg .u64 t; cvta.to.shared.u64 t, %1; cvt.u32.u64 %0, t; }" : "=r"(a) : "l"(p));
    return a;
}
__device__ __forceinline__ void ldm_x4(uint32_t* r, uint32_t addr) {
    asm volatile("ldmatrix.sync.aligned.m8n8.x4.shared.b16 {%0,%1,%2,%3}, [%4];"
                 : "=r"(r[0]), "=r"(r[1]), "=r"(r[2]), "=r"(r[3]) : "r"(addr));
}
__device__ __forceinline__ void mma16816(float* c, const uint32_t* a, const uint32_t* b) {
    asm volatile(
        "mma.sync.aligned.m16n8k16.row.col.f32.f16.f16.f32 "
        "{%0,%1,%2,%3}, {%4,%5,%6,%7}, {%8,%9}, {%0,%1,%2,%3};"
        : "+f"(c[0]), "+f"(c[1]), "+f"(c[2]), "+f"(c[3])
        : "r"(a[0]), "r"(a[1]), "r"(a[2]), "r"(a[3]), "r"(b[0]), "r"(b[1]));
}
__device__ __forceinline__ void cp16(uint32_t dst, const void* src) {
    asm volatile("cp.async.ca.shared.global [%0], [%1], 16;" :: "r"(dst), "l"(src) : "memory");
}
__device__ __forceinline__ void cp_commit() { asm volatile("cp.async.commit_group;" ::: "memory"); }
__device__ __forceinline__ void cp_wait0()  { asm volatile("cp.async.wait_group 0;"  ::: "memory"); }
__device__ __forceinline__ void cp_wait1()  { asm volatile("cp.async.wait_group 1;"  ::: "memory"); }

__device__ __forceinline__ void cvt_store_hi(float4 v, char* hip) {
    __half2 h01 = __floats2half2_rn(v.x, v.y);
    __half2 h23 = __floats2half2_rn(v.z, v.w);
    uint2 H; H.x = *(uint32_t*)&h01; H.y = *(uint32_t*)&h23;
    *(uint2*)hip = H;
}
__device__ __forceinline__ void cvt_store(float4 v, char* hip, char* lop) {
    __half2 h01 = __floats2half2_rn(v.x, v.y);
    __half2 h23 = __floats2half2_rn(v.z, v.w);
    float2  f01 = __half22float2(h01);
    float2  f23 = __half22float2(h23);
    __half2 l01 = __floats2half2_rn(v.x - f01.x, v.y - f01.y);
    __half2 l23 = __floats2half2_rn(v.z - f23.x, v.w - f23.y);
    uint2 H; H.x = *(uint32_t*)&h01; H.y = *(uint32_t*)&h23;
    uint2 L; L.x = *(uint32_t*)&l01; L.y = *(uint32_t*)&l23;
    *(uint2*)hip = H;
    *(uint2*)lop = L;
}
__device__ __forceinline__ unsigned enc_f(float s) {
    unsigned u = __float_as_uint(s);
    return (u & 0x80000000u) ? ~u : (u | 0x80000000u);
}
__device__ __forceinline__ float dec_f(unsigned u) {
    unsigned o = (u & 0x80000000u) ? (u & 0x7fffffffu) : ~u;
    return __uint_as_float(o);
}

// ---------------------------------------------------------------------------
// Prep: W1 split+transpose -> g_Whi/g_Wlo [u][k]
// ---------------------------------------------------------------------------
__global__ void wsplit_kernel(const float* __restrict__ W1)
{
    int i = blockIdx.x * 256 + threadIdx.x;
    int u = i >> 9, k = i & 511;
    float v = W1[(size_t)k * UU + u];
    __half h = __float2half_rn(v);
    __half l = __float2half_rn(v - __half2float(h));
    g_Whi[(size_t)u * FF + k] = h;
    g_Wlo[(size_t)u * FF + k] = l;
}

// ---------------------------------------------------------------------------
// Kernel A: APPROX scores, 1-term fp16 mma; 2 blocks/SM (R13 proven).
// ---------------------------------------------------------------------------
__global__ __launch_bounds__(NTH, 2)
void score_approx_kernel(const float* __restrict__ x,
                         const float* __restrict__ b1,
                         const float* __restrict__ W2,
                         const float* __restrict__ b2)
{
    extern __shared__ char smem[];
    const uint32_t sb = smem_u32(smem);
    const int tid  = threadIdx.x;
    const int lane = tid & 31;
    const int wid  = tid >> 5;
    const int wm   = wid & 3;
    const int wn   = wid >> 2;
    const int m0   = blockIdx.x * MBLK;

    int*   flags = (int*)(smem + SM_FLAGS);
    float* part  = (float*)(smem + SM_PART);
    float* w2s   = (float*)(smem + SM_W2);
    float* b1s   = (float*)(smem + SM_B1);

    if (tid < UU) { w2s[tid] = W2[tid]; b1s[tid] = b1[tid]; flags[tid] = 0; }

    const int la = lane & 7, lb = (lane >> 3) & 1, lc = lane >> 4;
    const uint32_t a_lane = (uint32_t)(la + lb * 8) * ROWB + (uint32_t)lc * 16;
    const uint32_t b_lane = (uint32_t)(la + lc * 8) * ROWB + (uint32_t)lb * 16;

    const float* xa = x + (size_t)m0 * FF;
    bool pr[2] = {false, false};

#pragma unroll
    for (int i = 0; i < 2; i++) {
        int idx = tid + i * NTH;
        int row = idx >> 3, c = idx & 7;
        float4 v = *(const float4*)(xa + (size_t)row * FF + c * 4);
        pr[i] = pr[i] || (v.x != 0.f || v.y != 0.f || v.z != 0.f || v.w != 0.f);
        cvt_store_hi(v, smem + SM_A(0) + row * ROWB + c * 8);
    }
    {
        int row = tid >> 2, c = tid & 3;
        cp16(sb + SM_B(0) + row * ROWB + c * 16, (const void*)(g_Whi + (size_t)row * FF + c * 8));
    }
    cp_commit(); cp_wait0();
    __syncthreads();

    float acc[2][4][4];
#pragma unroll
    for (int mt = 0; mt < 2; mt++)
#pragma unroll
        for (int nt = 0; nt < 4; nt++)
#pragma unroll
            for (int cc = 0; cc < 4; cc++) acc[mt][nt][cc] = 0.0f;

    for (int t = 0; t < NC; t++) {
        const int cb = t & 1, nb = cb ^ 1;
        const bool has_next = (t + 1 < NC);

        float4 rx[2];
        if (has_next) {
#pragma unroll
            for (int i = 0; i < 2; i++) {
                int idx = tid + i * NTH;
                int row = idx >> 3, c = idx & 7;
                rx[i] = *(const float4*)(xa + (size_t)row * FF + (t + 1) * KC + c * 4);
            }
            {
                int row = tid >> 2, c = tid & 3;
                cp16(sb + SM_B(nb) + row * ROWB + c * 16,
                     (const void*)(g_Whi + (size_t)row * FF + (t + 1) * KC + c * 8));
            }
            cp_commit();
        }

#pragma unroll
        for (int ks = 0; ks < 2; ks++) {
            const uint32_t kb = (uint32_t)ks * 32;
            uint32_t Ah[2][4];
            ldm_x4(Ah[0], sb + SM_A(cb) + (uint32_t)(wm*32 +  0) * ROWB + a_lane + kb);
            ldm_x4(Ah[1], sb + SM_A(cb) + (uint32_t)(wm*32 + 16) * ROWB + a_lane + kb);
#pragma unroll
            for (int p = 0; p < 2; p++) {
                uint32_t Bh[4];
                ldm_x4(Bh, sb + SM_B(cb) + (uint32_t)(wn*32 + p*16) * ROWB + b_lane + kb);
#pragma unroll
                for (int mt = 0; mt < 2; mt++) {
                    mma16816(acc[mt][2*p  ], Ah[mt], Bh + 0);
                    mma16816(acc[mt][2*p+1], Ah[mt], Bh + 2);
                }
            }
        }

        if (has_next) {
#pragma unroll
            for (int i = 0; i < 2; i++) {
                int idx = tid + i * NTH;
                int row = idx >> 3, c = idx & 7;
                float4 v = rx[i];
                pr[i] = pr[i] || (v.x != 0.f || v.y != 0.f || v.z != 0.f || v.w != 0.f);
                cvt_store_hi(v, smem + SM_A(nb) + row * ROWB + c * 8);
            }
            cp_wait0();
        }
        __syncthreads();
    }

#pragma unroll
    for (int i = 0; i < 2; i++)
        if (pr[i]) flags[(tid + i * NTH) >> 3] = 1;

    const float b2v = b2[0];
#pragma unroll
    for (int mt = 0; mt < 2; mt++) {
        float p0 = 0.f, p1 = 0.f;
#pragma unroll
        for (int nt = 0; nt < 4; nt++) {
            int u0 = wn * 32 + nt * 8 + (lane & 3) * 2;
            float w0 = w2s[u0], w1 = w2s[u0+1], c0 = b1s[u0], c1 = b1s[u0+1];
            p0 += fmaxf(acc[mt][nt][0] + c0, 0.f) * w0 + fmaxf(acc[mt][nt][1] + c1, 0.f) * w1;
            p1 += fmaxf(acc[mt][nt][2] + c0, 0.f) * w0 + fmaxf(acc[mt][nt][3] + c1, 0.f) * w1;
        }
        p0 += __shfl_xor_sync(0xffffffffu, p0, 1);
        p0 += __shfl_xor_sync(0xffffffffu, p0, 2);
        p1 += __shfl_xor_sync(0xffffffffu, p1, 1);
        p1 += __shfl_xor_sync(0xffffffffu, p1, 2);
        if ((lane & 3) == 0) {
            int r = lane >> 2;
            part[(wm*32 + mt*16 +     r) * 4 + wn] = p0;
            part[(wm*32 + mt*16 + 8 + r) * 4 + wn] = p1;
        }
    }
    __syncthreads();
    if (tid < MBLK) {
        float s = part[tid*4] + part[tid*4+1] + part[tid*4+2] + part[tid*4+3] + b2v;
        g_scores[m0 + tid] = flags[tid] ? s : NEG_BIG;
    }
}

// ---------------------------------------------------------------------------
// Kernel B: RADIX-SELECT top-k threshold + unordered candidate compaction.
// ---------------------------------------------------------------------------
__global__ __launch_bounds__(512)
void topk_kernel(const int* __restrict__ kptr)
{
    __shared__ unsigned key[TT];
    __shared__ int hist[256];
    __shared__ int Sarr[257];
    __shared__ int wtot[8];
    __shared__ unsigned s_prefix;
    __shared__ int s_rank, s_bin, s_cnt;

    const int b   = blockIdx.x;
    const int tid = threadIdx.x;
    const int lane = tid & 31;

    for (int t = tid; t < TT; t += 512)
        key[t] = enc_f(g_scores[b * TT + t]);
    ((int*)g_sel)[b * (TT / 4) + tid] = 0;
    if (tid == 0) { s_rank = *kptr; s_prefix = 0; s_cnt = 0; }
    __syncthreads();

#pragma unroll
    for (int p = 0; p < 4; p++) {
        const int shift = 24 - 8 * p;
        if (tid < 256) hist[tid] = 0;
        __syncthreads();
        const unsigned pref = s_prefix;
        for (int t = tid; t < TT; t += 512) {
            unsigned kv = key[t];
            if (p == 0 || (kv >> (shift + 8)) == pref)
                atomicAdd(&hist[(kv >> shift) & 0xFF], 1);
        }
        __syncthreads();
        if (tid < 256) {
            int val = hist[tid];
#pragma unroll
            for (int off = 1; off < 32; off <<= 1) {
                int n = __shfl_down_sync(0xffffffffu, val, off);
                if (lane + off < 32) val += n;
            }
            Sarr[tid] = val;
            if (lane == 0) wtot[tid >> 5] = val;
        }
        __syncthreads();
        if (tid < 256) {
            int w = tid >> 5, add = 0;
#pragma unroll
            for (int v = 7; v > 0; v--) if (v > w) add += wtot[v];
            Sarr[tid] += add;
        }
        if (tid == 0) Sarr[256] = 0;
        __syncthreads();
        const int r = s_rank;
        if (tid < 256) {
            if (Sarr[tid] >= r && Sarr[tid + 1] < r) s_bin = tid;
        }
        __syncthreads();
        if (tid == 0) {
            int bs = s_bin;
            s_rank   = s_rank - Sarr[bs + 1];
            s_prefix = (s_prefix << 8) | (unsigned)bs;
        }
        __syncthreads();
    }

    const unsigned kth_u  = s_prefix;
    const unsigned cthr_u = enc_f(dec_f(kth_u) - BAND);

    for (int t = tid; t < TT; t += 512) {
        if (key[t] >= cthr_u) {
            int pos = atomicAdd(&s_cnt, 1);
            if (pos < CAP) g_cand[b * CAP + pos] = t;
        }
    }
    __syncthreads();
    int C = s_cnt; if (C > CAP) C = CAP;
    if (tid < CAP && tid >= C) g_cand[b * CAP + tid] = -1;
}

// ---------------------------------------------------------------------------
// Kernel C: EXACT rescore (3-term fp16 split), 16 frames/block, grid 256.
// Early-exit for all-invalid quarters (candidates are compacted).
// ---------------------------------------------------------------------------
__global__ __launch_bounds__(256, 2)
void rescore_kernel(const float* __restrict__ x,
                    const float* __restrict__ b1,
                    const float* __restrict__ W2,
                    const float* __restrict__ b2)
{
    extern __shared__ char smem[];
    const uint32_t sb = smem_u32(smem);
    const int tid = threadIdx.x, lane = tid & 31, w = tid >> 5;
    const int b = blockIdx.x >> 3, q = blockIdx.x & 7;

    // early-exit: candidates are a compacted prefix; if the first slot of this
    // quarter is -1, the whole quarter is invalid. (Checked BEFORE any cp.async.)
    if (g_cand[b * CAP + q * 16] < 0) {
        if (tid < 16) g_exact[b * CAP + q * 16 + tid] = NEG_BIG;
        return;
    }

    int*   flags = (int*)(smem + R_FLAGS);
    float* part  = (float*)(smem + R_PART);
    float* w2s   = (float*)(smem + R_W2);
    float* b1s   = (float*)(smem + R_B1);

    // issue B chunk kc into stage s (one commit group: hi + lo)
    auto issueB = [&](int s, int kc) {
#pragma unroll
        for (int j = 0; j < 4; j++) {
            int idx = tid + j * 256;
            int rr = idx >> 3, cc = idx & 7;
            cp16(sb + R_B(s,0) + rr * R_ROWB + cc * 16,
                 (const void*)(g_Whi + (size_t)rr * FF + kc * 64 + cc * 8));
            cp16(sb + R_B(s,1) + rr * R_ROWB + cc * 16,
                 (const void*)(g_Wlo + (size_t)rr * FF + kc * 64 + cc * 8));
        }
        cp_commit();
    };

    // start W stream immediately (latency overlaps the A gather below)
    issueB(0, 0);
    issueB(1, 1);

    if (tid < UU) { w2s[tid] = W2[tid]; b1s[tid] = b1[tid]; }
    if (tid < 16) flags[tid] = 0;
    __syncthreads();

    // gather 16 candidate frames into A (hi/lo); 16 threads per frame
    {
        int row = tid >> 4, l16 = tid & 15;
        int frame = g_cand[b * CAP + q * 16 + row];
        bool valid = frame >= 0;
        int f = valid ? frame : 0;
        const float4* xr = (const float4*)(x + ((size_t)b * TT + f) * FF);
        bool nz = false;
#pragma unroll
        for (int i = 0; i < 8; i++) {
            int i4 = l16 * 8 + i;
            float4 v = xr[i4];
            nz = nz || (v.x != 0.f || v.y != 0.f || v.z != 0.f || v.w != 0.f);
            cvt_store(v, smem + R_AHI + row * R_ROWA + i4 * 8,
                         smem + R_ALO + row * R_ROWA + i4 * 8);
        }
        if (valid && nz) atomicOr(&flags[row], 1);
    }

    const int la = lane & 7, lb = (lane >> 3) & 1, lc = lane >> 4;
    const uint32_t a_lane = (uint32_t)(la + lb * 8) * R_ROWA + (uint32_t)lc * 16;
    const uint32_t b_lane = (uint32_t)(la + lc * 8) * R_ROWB + (uint32_t)lb * 16;

    float acc[2][4];
#pragma unroll
    for (int nt = 0; nt < 2; nt++)
#pragma unroll
        for (int cc = 0; cc < 4; cc++) acc[nt][cc] = 0.0f;

    for (int kc = 0; kc < 8; kc++) {
        const int s = kc & 1;
        if (kc < 7) cp_wait1(); else cp_wait0();   // chunk kc's group complete
        __syncthreads();                            // visibility + A ready (kc=0)

#pragma unroll
        for (int ks = 0; ks < 4; ks++) {
            uint32_t kbA = (uint32_t)(kc * 128 + ks * 32);
            uint32_t kbB = (uint32_t)(ks * 32);
            uint32_t Ah[4], Al[4], Bh[4], Bl[4];
            ldm_x4(Ah, sb + R_AHI + a_lane + kbA);
            ldm_x4(Al, sb + R_ALO + a_lane + kbA);
            ldm_x4(Bh, sb + R_B(s,0) + (uint32_t)(w * 16) * R_ROWB + b_lane + kbB);
            ldm_x4(Bl, sb + R_B(s,1) + (uint32_t)(w * 16) * R_ROWB + b_lane + kbB);
            mma16816(acc[0], Ah, Bh + 0);
            mma16816(acc[1], Ah, Bh + 2);
            mma16816(acc[0], Ah, Bl + 0);
            mma16816(acc[1], Ah, Bl + 2);
            mma16816(acc[0], Al, Bh + 0);
            mma16816(acc[1], Al, Bh + 2);
        }

        if (kc + 2 < 8) {
            __syncthreads();            // all warps done reading stage s
            issueB(s, kc + 2);          // refill stage s with chunk kc+2
        }
    }
    __syncthreads();

    const float b2v = b2[0];
    {
        float p0 = 0.f, p1 = 0.f;
#pragma unroll
        for (int nt = 0; nt < 2; nt++) {
            int u0 = w * 16 + nt * 8 + (lane & 3) * 2;
            float w0 = w2s[u0], w1 = w2s[u0+1], c0 = b1s[u0], c1 = b1s[u0+1];
            p0 += fmaxf(acc[nt][0] + c0, 0.f) * w0 + fmaxf(acc[nt][1] + c1, 0.f) * w1;
            p1 += fmaxf(acc[nt][2] + c0, 0.f) * w0 + fmaxf(acc[nt][3] + c1, 0.f) * w1;
        }
        p0 += __shfl_xor_sync(0xffffffffu, p0, 1);
        p0 += __shfl_xor_sync(0xffffffffu, p0, 2);
        p1 += __shfl_xor_sync(0xffffffffu, p1, 1);
        p1 += __shfl_xor_sync(0xffffffffu, p1, 2);
        if ((lane & 3) == 0) {
            int r = lane >> 2;
            part[(    r) * 8 + w] = p0;
            part[(8 + r) * 8 + w] = p1;
        }
    }
    __syncthreads();
    if (tid < 16) {
        float s = b2v;
#pragma unroll
        for (int j = 0; j < 8; j++) s += part[tid * 8 + j];
        g_exact[b * CAP + q * 16 + tid] = flags[tid] ? s : NEG_BIG;
    }
}

// ---------------------------------------------------------------------------
// Kernel D: exact top-k among <=128 candidates -> sel mask.
// ---------------------------------------------------------------------------
__global__ __launch_bounds__(128)
void select_kernel(const int* __restrict__ kptr)
{
    __shared__ unsigned long long keys[CAP];
    const int b = blockIdx.x, tid = threadIdx.x;

    {
        float s = g_exact[b * CAP + tid];
        int fr = g_cand[b * CAP + tid];
        unsigned low = (fr >= 0) ? ~(unsigned)fr : 0u;
        keys[tid] = ((unsigned long long)enc_f(s) << 32) | low;
    }
    __syncthreads();

    for (int kk = 2; kk <= CAP; kk <<= 1) {
        for (int j = kk >> 1; j > 0; j >>= 1) {
            int i = tid, ixj = i ^ j;
            if (ixj > i) {
                unsigned long long a = keys[i], c = keys[ixj];
                bool desc = ((i & kk) == 0);
                if (desc ? (a < c) : (a > c)) { keys[i] = c; keys[ixj] = a; }
            }
            __syncthreads();
        }
    }

    const int k = *kptr;
    if (tid < k) {
        int fr = (int)(~(unsigned)(keys[tid] & 0xffffffffu));
        if (fr >= 0 && fr < TT) g_sel[b * TT + fr] = 1;
    }
}

// ---------------------------------------------------------------------------
// Kernel E: out = x * sel (proven form).
// ---------------------------------------------------------------------------
__global__ __launch_bounds__(256)
void gather_kernel(const float* __restrict__ x, float* __restrict__ out)
{
    const long long idx = (long long)blockIdx.x * blockDim.x + threadIdx.x;
    const int frame = (int)(idx >> 7);
    float4 o = make_float4(0.f, 0.f, 0.f, 0.f);
    if (g_sel[frame])
        o = ((const float4*)x)[idx];
    ((float4*)out)[idx] = o;
}

// ---------------------------------------------------------------------------
extern "C" void kernel_launch(void* const* d_in, const int* in_sizes, int n_in,
                              void* d_out, int out_size)
{
    const float* x  = (const float*)d_in[0];
    const float* W1 = (const float*)d_in[1];
    const float* b1 = (const float*)d_in[2];
    const float* W2 = (const float*)d_in[3];
    const float* b2 = (const float*)d_in[4];
    const int*   kp = (const int*)d_in[5];
    float* out = (float*)d_out;

    cudaFuncSetAttribute(score_approx_kernel,
                         cudaFuncAttributeMaxDynamicSharedMemorySize, SM_TOTAL);
    cudaFuncSetAttribute(rescore_kernel,
                         cudaFuncAttributeMaxDynamicSharedMemorySize, R_TOTAL);

    wsplit_kernel<<<UU * FF / 256, 256>>>(W1);
    score_approx_kernel<<<NBLK, NTH, SM_TOTAL>>>(x, b1, W2, b2);
    topk_kernel<<<BB, 512>>>(kp);
    rescore_kernel<<<BB * 8, 256, R_TOTAL>>>(x, b1, W2, b2);
    select_kernel<<<BB, 128>>>(kp);
    const long long nvec4 = (long long)MM * FF / 4;
    gather_kernel<<<(unsigned)(nvec4 / 256), 256>>>(x, out);
}

// round 17
// speedup vs baseline: 1.1005x; 1.1005x over previous
#include <cuda_runtime.h>
#include <cuda_fp16.h>
#include <cstdint>

// Problem constants
#define BB   32
#define TT   2048
#define FF   512
#define UU   128
#define MM   (BB * TT)
#define NEG_BIG -1.0e9f
#define CAP  128               // candidate cap per row
#define BAND 4.0e-3f           // approx-score safety band

// approx score kernel tiling
#define MBLK 128
#define KC   32
#define NC   (FF / KC)         // 16
#define NTH  512               // 16 warps: 4 m x 4 n
#define NBLK (MM / MBLK)       // 512

#define ROWB  80
#define ATILE (128 * ROWB)     // 10240
#define SM_A(b)  ((b) * ATILE)
#define SM_B(b)  (20480 + (b) * ATILE)
#define SM_FLAGS 40960
#define SM_PART  41472
#define SM_W2    43520
#define SM_B1    44032
#define SM_TOTAL 44544

// rescore kernel smem (16-frame tiles, 2-stage cp.async B pipeline)
#define R_ROWA  1040
#define R_ROWB  144
#define R_AHI   0
#define R_ALO   (16 * R_ROWA)
#define R_BSTG  18432
#define R_B(s,h) (33280 + ((s) * 2 + (h)) * R_BSTG)
#define R_FLAGS 107008
#define R_PART  (R_FLAGS + 64)
#define R_W2    (R_PART + 512)
#define R_B1    (R_W2 + 512)
#define R_TOTAL (R_B1 + 512)               // 108608 -> 2 blocks/SM

#define RBLK   (BB * 8)                    // 256 rescore blocks
#define ZBLK   512                         // zero-fill blocks appended
#define ZF4    16384                       // float4 per zero block (128MB total)

// Static scratch
__device__ float          g_scores[MM];
__device__ __half         g_Whi[UU * FF];
__device__ __half         g_Wlo[UU * FF];
__device__ int            g_cand[BB * CAP];
__device__ float          g_exact[BB * CAP];
__device__ int            g_topidx[BB * CAP];

// ---------------- PTX helpers ----------------
__device__ __forceinline__ uint32_t smem_u32(const void* p) {
    uint32_t a;
    asm("{ .reg .u64 t; cvta.to.shared.u64 t, %1; cvt.u32.u64 %0, t; }" : "=r"(a) : "l"(p));
    return a;
}
__device__ __forceinline__ void ldm_x4(uint32_t* r, uint32_t addr) {
    asm volatile("ldmatrix.sync.aligned.m8n8.x4.shared.b16 {%0,%1,%2,%3}, [%4];"
                 : "=r"(r[0]), "=r"(r[1]), "=r"(r[2]), "=r"(r[3]) : "r"(addr));
}
__device__ __forceinline__ void mma16816(float* c, const uint32_t* a, const uint32_t* b) {
    asm volatile(
        "mma.sync.aligned.m16n8k16.row.col.f32.f16.f16.f32 "
        "{%0,%1,%2,%3}, {%4,%5,%6,%7}, {%8,%9}, {%0,%1,%2,%3};"
        : "+f"(c[0]), "+f"(c[1]), "+f"(c[2]), "+f"(c[3])
        : "r"(a[0]), "r"(a[1]), "r"(a[2]), "r"(a[3]), "r"(b[0]), "r"(b[1]));
}
__device__ __forceinline__ void cp16(uint32_t dst, const void* src) {
    asm volatile("cp.async.ca.shared.global [%0], [%1], 16;" :: "r"(dst), "l"(src) : "memory");
}
__device__ __forceinline__ void cp_commit() { asm volatile("cp.async.commit_group;" ::: "memory"); }
__device__ __forceinline__ void cp_wait0()  { asm volatile("cp.async.wait_group 0;"  ::: "memory"); }
__device__ __forceinline__ void cp_wait1()  { asm volatile("cp.async.wait_group 1;"  ::: "memory"); }

__device__ __forceinline__ void cvt_store_hi(float4 v, char* hip) {
    __half2 h01 = __floats2half2_rn(v.x, v.y);
    __half2 h23 = __floats2half2_rn(v.z, v.w);
    uint2 H; H.x = *(uint32_t*)&h01; H.y = *(uint32_t*)&h23;
    *(uint2*)hip = H;
}
__device__ __forceinline__ void cvt_store(float4 v, char* hip, char* lop) {
    __half2 h01 = __floats2half2_rn(v.x, v.y);
    __half2 h23 = __floats2half2_rn(v.z, v.w);
    float2  f01 = __half22float2(h01);
    float2  f23 = __half22float2(h23);
    __half2 l01 = __floats2half2_rn(v.x - f01.x, v.y - f01.y);
    __half2 l23 = __floats2half2_rn(v.z - f23.x, v.w - f23.y);
    uint2 H; H.x = *(uint32_t*)&h01; H.y = *(uint32_t*)&h23;
    uint2 L; L.x = *(uint32_t*)&l01; L.y = *(uint32_t*)&l23;
    *(uint2*)hip = H;
    *(uint2*)lop = L;
}
__device__ __forceinline__ unsigned enc_f(float s) {
    unsigned u = __float_as_uint(s);
    return (u & 0x80000000u) ? ~u : (u | 0x80000000u);
}
__device__ __forceinline__ float dec_f(unsigned u) {
    unsigned o = (u & 0x80000000u) ? (u & 0x7fffffffu) : ~u;
    return __uint_as_float(o);
}

// ---------------------------------------------------------------------------
// Prep: W1 split+transpose -> g_Whi/g_Wlo [u][k]
// ---------------------------------------------------------------------------
__global__ void wsplit_kernel(const float* __restrict__ W1)
{
    int i = blockIdx.x * 256 + threadIdx.x;
    int u = i >> 9, k = i & 511;
    float v = W1[(size_t)k * UU + u];
    __half h = __float2half_rn(v);
    __half l = __float2half_rn(v - __half2float(h));
    g_Whi[(size_t)u * FF + k] = h;
    g_Wlo[(size_t)u * FF + k] = l;
}

// ---------------------------------------------------------------------------
// Kernel A: APPROX scores, 1-term fp16 mma; 2 blocks/SM (proven).
// ---------------------------------------------------------------------------
__global__ __launch_bounds__(NTH, 2)
void score_approx_kernel(const float* __restrict__ x,
                         const float* __restrict__ b1,
                         const float* __restrict__ W2,
                         const float* __restrict__ b2)
{
    extern __shared__ char smem[];
    const uint32_t sb = smem_u32(smem);
    const int tid  = threadIdx.x;
    const int lane = tid & 31;
    const int wid  = tid >> 5;
    const int wm   = wid & 3;
    const int wn   = wid >> 2;
    const int m0   = blockIdx.x * MBLK;

    int*   flags = (int*)(smem + SM_FLAGS);
    float* part  = (float*)(smem + SM_PART);
    float* w2s   = (float*)(smem + SM_W2);
    float* b1s   = (float*)(smem + SM_B1);

    if (tid < UU) { w2s[tid] = W2[tid]; b1s[tid] = b1[tid]; flags[tid] = 0; }

    const int la = lane & 7, lb = (lane >> 3) & 1, lc = lane >> 4;
    const uint32_t a_lane = (uint32_t)(la + lb * 8) * ROWB + (uint32_t)lc * 16;
    const uint32_t b_lane = (uint32_t)(la + lc * 8) * ROWB + (uint32_t)lb * 16;

    const float* xa = x + (size_t)m0 * FF;
    bool pr[2] = {false, false};

#pragma unroll
    for (int i = 0; i < 2; i++) {
        int idx = tid + i * NTH;
        int row = idx >> 3, c = idx & 7;
        float4 v = *(const float4*)(xa + (size_t)row * FF + c * 4);
        pr[i] = pr[i] || (v.x != 0.f || v.y != 0.f || v.z != 0.f || v.w != 0.f);
        cvt_store_hi(v, smem + SM_A(0) + row * ROWB + c * 8);
    }
    {
        int row = tid >> 2, c = tid & 3;
        cp16(sb + SM_B(0) + row * ROWB + c * 16, (const void*)(g_Whi + (size_t)row * FF + c * 8));
    }
    cp_commit(); cp_wait0();
    __syncthreads();

    float acc[2][4][4];
#pragma unroll
    for (int mt = 0; mt < 2; mt++)
#pragma unroll
        for (int nt = 0; nt < 4; nt++)
#pragma unroll
            for (int cc = 0; cc < 4; cc++) acc[mt][nt][cc] = 0.0f;

    for (int t = 0; t < NC; t++) {
        const int cb = t & 1, nb = cb ^ 1;
        const bool has_next = (t + 1 < NC);

        float4 rx[2];
        if (has_next) {
#pragma unroll
            for (int i = 0; i < 2; i++) {
                int idx = tid + i * NTH;
                int row = idx >> 3, c = idx & 7;
                rx[i] = *(const float4*)(xa + (size_t)row * FF + (t + 1) * KC + c * 4);
            }
            {
                int row = tid >> 2, c = tid & 3;
                cp16(sb + SM_B(nb) + row * ROWB + c * 16,
                     (const void*)(g_Whi + (size_t)row * FF + (t + 1) * KC + c * 8));
            }
            cp_commit();
        }

#pragma unroll
        for (int ks = 0; ks < 2; ks++) {
            const uint32_t kb = (uint32_t)ks * 32;
            uint32_t Ah[2][4];
            ldm_x4(Ah[0], sb + SM_A(cb) + (uint32_t)(wm*32 +  0) * ROWB + a_lane + kb);
            ldm_x4(Ah[1], sb + SM_A(cb) + (uint32_t)(wm*32 + 16) * ROWB + a_lane + kb);
#pragma unroll
            for (int p = 0; p < 2; p++) {
                uint32_t Bh[4];
                ldm_x4(Bh, sb + SM_B(cb) + (uint32_t)(wn*32 + p*16) * ROWB + b_lane + kb);
#pragma unroll
                for (int mt = 0; mt < 2; mt++) {
                    mma16816(acc[mt][2*p  ], Ah[mt], Bh + 0);
                    mma16816(acc[mt][2*p+1], Ah[mt], Bh + 2);
                }
            }
        }

        if (has_next) {
#pragma unroll
            for (int i = 0; i < 2; i++) {
                int idx = tid + i * NTH;
                int row = idx >> 3, c = idx & 7;
                float4 v = rx[i];
                pr[i] = pr[i] || (v.x != 0.f || v.y != 0.f || v.z != 0.f || v.w != 0.f);
                cvt_store_hi(v, smem + SM_A(nb) + row * ROWB + c * 8);
            }
            cp_wait0();
        }
        __syncthreads();
    }

#pragma unroll
    for (int i = 0; i < 2; i++)
        if (pr[i]) flags[(tid + i * NTH) >> 3] = 1;

    const float b2v = b2[0];
#pragma unroll
    for (int mt = 0; mt < 2; mt++) {
        float p0 = 0.f, p1 = 0.f;
#pragma unroll
        for (int nt = 0; nt < 4; nt++) {
            int u0 = wn * 32 + nt * 8 + (lane & 3) * 2;
            float w0 = w2s[u0], w1 = w2s[u0+1], c0 = b1s[u0], c1 = b1s[u0+1];
            p0 += fmaxf(acc[mt][nt][0] + c0, 0.f) * w0 + fmaxf(acc[mt][nt][1] + c1, 0.f) * w1;
            p1 += fmaxf(acc[mt][nt][2] + c0, 0.f) * w0 + fmaxf(acc[mt][nt][3] + c1, 0.f) * w1;
        }
        p0 += __shfl_xor_sync(0xffffffffu, p0, 1);
        p0 += __shfl_xor_sync(0xffffffffu, p0, 2);
        p1 += __shfl_xor_sync(0xffffffffu, p1, 1);
        p1 += __shfl_xor_sync(0xffffffffu, p1, 2);
        if ((lane & 3) == 0) {
            int r = lane >> 2;
            part[(wm*32 + mt*16 +     r) * 4 + wn] = p0;
            part[(wm*32 + mt*16 + 8 + r) * 4 + wn] = p1;
        }
    }
    __syncthreads();
    if (tid < MBLK) {
        float s = part[tid*4] + part[tid*4+1] + part[tid*4+2] + part[tid*4+3] + b2v;
        g_scores[m0 + tid] = flags[tid] ? s : NEG_BIG;
    }
}

// ---------------------------------------------------------------------------
// Kernel B: RADIX-SELECT top-k threshold + unordered candidate compaction.
// ---------------------------------------------------------------------------
__global__ __launch_bounds__(512)
void topk_kernel(const int* __restrict__ kptr)
{
    __shared__ unsigned key[TT];
    __shared__ int hist[256];
    __shared__ int Sarr[257];
    __shared__ int wtot[8];
    __shared__ unsigned s_prefix;
    __shared__ int s_rank, s_bin, s_cnt;

    const int b   = blockIdx.x;
    const int tid = threadIdx.x;
    const int lane = tid & 31;

    for (int t = tid; t < TT; t += 512)
        key[t] = enc_f(g_scores[b * TT + t]);
    if (tid == 0) { s_rank = *kptr; s_prefix = 0; s_cnt = 0; }
    __syncthreads();

#pragma unroll
    for (int p = 0; p < 4; p++) {
        const int shift = 24 - 8 * p;
        if (tid < 256) hist[tid] = 0;
        __syncthreads();
        const unsigned pref = s_prefix;
        for (int t = tid; t < TT; t += 512) {
            unsigned kv = key[t];
            if (p == 0 || (kv >> (shift + 8)) == pref)
                atomicAdd(&hist[(kv >> shift) & 0xFF], 1);
        }
        __syncthreads();
        if (tid < 256) {
            int val = hist[tid];
#pragma unroll
            for (int off = 1; off < 32; off <<= 1) {
                int n = __shfl_down_sync(0xffffffffu, val, off);
                if (lane + off < 32) val += n;
            }
            Sarr[tid] = val;
            if (lane == 0) wtot[tid >> 5] = val;
        }
        __syncthreads();
        if (tid < 256) {
            int w = tid >> 5, add = 0;
#pragma unroll
            for (int v = 7; v > 0; v--) if (v > w) add += wtot[v];
            Sarr[tid] += add;
        }
        if (tid == 0) Sarr[256] = 0;
        __syncthreads();
        const int r = s_rank;
        if (tid < 256) {
            if (Sarr[tid] >= r && Sarr[tid + 1] < r) s_bin = tid;
        }
        __syncthreads();
        if (tid == 0) {
            int bs = s_bin;
            s_rank   = s_rank - Sarr[bs + 1];
            s_prefix = (s_prefix << 8) | (unsigned)bs;
        }
        __syncthreads();
    }

    const unsigned kth_u  = s_prefix;
    const unsigned cthr_u = enc_f(dec_f(kth_u) - BAND);

    for (int t = tid; t < TT; t += 512) {
        if (key[t] >= cthr_u) {
            int pos = atomicAdd(&s_cnt, 1);
            if (pos < CAP) g_cand[b * CAP + pos] = t;
        }
    }
    __syncthreads();
    int C = s_cnt; if (C > CAP) C = CAP;
    if (tid < CAP && tid >= C) g_cand[b * CAP + tid] = -1;
}

// ---------------------------------------------------------------------------
// Kernel C: EXACT rescore (3-term fp16 split) + co-scheduled zero-fill.
// Blocks [0, RBLK): rescore quarters (early-exit on dead quarters).
// Blocks [RBLK, RBLK+ZBLK): stream zeros into out (no dependency).
// ---------------------------------------------------------------------------
__global__ __launch_bounds__(256, 2)
void rescore_kernel(const float* __restrict__ x,
                    const float* __restrict__ b1,
                    const float* __restrict__ W2,
                    const float* __restrict__ b2,
                    float4* __restrict__ out4)
{
    extern __shared__ char smem[];
    const uint32_t sb = smem_u32(smem);
    const int tid = threadIdx.x, lane = tid & 31, w = tid >> 5;

    // ---- zero-fill blocks: pure 128MB store stream on idle SMs ----
    if (blockIdx.x >= RBLK) {
        const long long zb = blockIdx.x - RBLK;          // 0..ZBLK-1
        float4* dst = out4 + zb * ZF4;
        const float4 z = make_float4(0.f, 0.f, 0.f, 0.f);
#pragma unroll 8
        for (int j = 0; j < 64; j++)
            dst[j * 256 + tid] = z;
        return;
    }

    const int b = blockIdx.x >> 3, q = blockIdx.x & 7;

    // early-exit: compacted candidates => first slot -1 means whole quarter dead
    if (g_cand[b * CAP + q * 16] < 0) {
        if (tid < 16) g_exact[b * CAP + q * 16 + tid] = NEG_BIG;
        return;
    }

    int*   flags = (int*)(smem + R_FLAGS);
    float* part  = (float*)(smem + R_PART);
    float* w2s   = (float*)(smem + R_W2);
    float* b1s   = (float*)(smem + R_B1);

    auto issueB = [&](int s, int kc) {
#pragma unroll
        for (int j = 0; j < 4; j++) {
            int idx = tid + j * 256;
            int rr = idx >> 3, cc = idx & 7;
            cp16(sb + R_B(s,0) + rr * R_ROWB + cc * 16,
                 (const void*)(g_Whi + (size_t)rr * FF + kc * 64 + cc * 8));
            cp16(sb + R_B(s,1) + rr * R_ROWB + cc * 16,
                 (const void*)(g_Wlo + (size_t)rr * FF + kc * 64 + cc * 8));
        }
        cp_commit();
    };

    issueB(0, 0);
    issueB(1, 1);

    if (tid < UU) { w2s[tid] = W2[tid]; b1s[tid] = b1[tid]; }
    if (tid < 16) flags[tid] = 0;
    __syncthreads();

    {
        int row = tid >> 4, l16 = tid & 15;
        int frame = g_cand[b * CAP + q * 16 + row];
        bool valid = frame >= 0;
        int f = valid ? frame : 0;
        const float4* xr = (const float4*)(x + ((size_t)b * TT + f) * FF);
        bool nz = false;
#pragma unroll
        for (int i = 0; i < 8; i++) {
            int i4 = l16 * 8 + i;
            float4 v = xr[i4];
            nz = nz || (v.x != 0.f || v.y != 0.f || v.z != 0.f || v.w != 0.f);
            cvt_store(v, smem + R_AHI + row * R_ROWA + i4 * 8,
                         smem + R_ALO + row * R_ROWA + i4 * 8);
        }
        if (valid && nz) atomicOr(&flags[row], 1);
    }

    const int la = lane & 7, lb = (lane >> 3) & 1, lc = lane >> 4;
    const uint32_t a_lane = (uint32_t)(la + lb * 8) * R_ROWA + (uint32_t)lc * 16;
    const uint32_t b_lane = (uint32_t)(la + lc * 8) * R_ROWB + (uint32_t)lb * 16;

    float acc[2][4];
#pragma unroll
    for (int nt = 0; nt < 2; nt++)
#pragma unroll
        for (int cc = 0; cc < 4; cc++) acc[nt][cc] = 0.0f;

    for (int kc = 0; kc < 8; kc++) {
        const int s = kc & 1;
        if (kc < 7) cp_wait1(); else cp_wait0();
        __syncthreads();

#pragma unroll
        for (int ks = 0; ks < 4; ks++) {
            uint32_t kbA = (uint32_t)(kc * 128 + ks * 32);
            uint32_t kbB = (uint32_t)(ks * 32);
            uint32_t Ah[4], Al[4], Bh[4], Bl[4];
            ldm_x4(Ah, sb + R_AHI + a_lane + kbA);
            ldm_x4(Al, sb + R_ALO + a_lane + kbA);
            ldm_x4(Bh, sb + R_B(s,0) + (uint32_t)(w * 16) * R_ROWB + b_lane + kbB);
            ldm_x4(Bl, sb + R_B(s,1) + (uint32_t)(w * 16) * R_ROWB + b_lane + kbB);
            mma16816(acc[0], Ah, Bh + 0);
            mma16816(acc[1], Ah, Bh + 2);
            mma16816(acc[0], Ah, Bl + 0);
            mma16816(acc[1], Ah, Bl + 2);
            mma16816(acc[0], Al, Bh + 0);
            mma16816(acc[1], Al, Bh + 2);
        }

        if (kc + 2 < 8) {
            __syncthreads();
            issueB(s, kc + 2);
        }
    }
    __syncthreads();

    const float b2v = b2[0];
    {
        float p0 = 0.f, p1 = 0.f;
#pragma unroll
        for (int nt = 0; nt < 2; nt++) {
            int u0 = w * 16 + nt * 8 + (lane & 3) * 2;
            float w0 = w2s[u0], w1 = w2s[u0+1], c0 = b1s[u0], c1 = b1s[u0+1];
            p0 += fmaxf(acc[nt][0] + c0, 0.f) * w0 + fmaxf(acc[nt][1] + c1, 0.f) * w1;
            p1 += fmaxf(acc[nt][2] + c0, 0.f) * w0 + fmaxf(acc[nt][3] + c1, 0.f) * w1;
        }
        p0 += __shfl_xor_sync(0xffffffffu, p0, 1);
        p0 += __shfl_xor_sync(0xffffffffu, p0, 2);
        p1 += __shfl_xor_sync(0xffffffffu, p1, 1);
        p1 += __shfl_xor_sync(0xffffffffu, p1, 2);
        if ((lane & 3) == 0) {
            int r = lane >> 2;
            part[(    r) * 8 + w] = p0;
            part[(8 + r) * 8 + w] = p1;
        }
    }
    __syncthreads();
    if (tid < 16) {
        float s = b2v;
#pragma unroll
        for (int j = 0; j < 8; j++) s += part[tid * 8 + j];
        g_exact[b * CAP + q * 16 + tid] = flags[tid] ? s : NEG_BIG;
    }
}

// ---------------------------------------------------------------------------
// Kernel D: exact top-k among <=128 candidates -> compact top index list.
// ---------------------------------------------------------------------------
__global__ __launch_bounds__(128)
void select_kernel(const int* __restrict__ kptr)
{
    __shared__ unsigned long long keys[CAP];
    const int b = blockIdx.x, tid = threadIdx.x;

    {
        float s = g_exact[b * CAP + tid];
        int fr = g_cand[b * CAP + tid];
        unsigned low = (fr >= 0) ? ~(unsigned)fr : 0u;
        keys[tid] = ((unsigned long long)enc_f(s) << 32) | low;
    }
    __syncthreads();

    for (int kk = 2; kk <= CAP; kk <<= 1) {
        for (int j = kk >> 1; j > 0; j >>= 1) {
            int i = tid, ixj = i ^ j;
            if (ixj > i) {
                unsigned long long a = keys[i], c = keys[ixj];
                bool desc = ((i & kk) == 0);
                if (desc ? (a < c) : (a > c)) { keys[i] = c; keys[ixj] = a; }
            }
            __syncthreads();
        }
    }

    const int k = *kptr;
    if (tid < k && tid < CAP) {
        int fr = (int)(~(unsigned)(keys[tid] & 0xffffffffu));
        g_topidx[b * CAP + tid] = (fr >= 0 && fr < TT) ? fr : 0;
    }
}

// ---------------------------------------------------------------------------
// Kernel E: scatter-copy only the selected frames (~4MB). Zeros already
// written by rescore_kernel's zero-fill blocks.
// ---------------------------------------------------------------------------
__global__ __launch_bounds__(128)
void scatter_kernel(const float* __restrict__ x, float* __restrict__ out,
                    const int* __restrict__ kptr)
{
    const int b    = blockIdx.x;
    const int part = blockIdx.y;
    const int tid  = threadIdx.x;
    const int k    = *kptr;

    for (int r = part; r < k && r < CAP; r += 16) {
        int frame = g_topidx[b * CAP + r];
        const float4* src = (const float4*)(x   + ((size_t)b * TT + frame) * FF);
        float4*       dst = (float4*)      (out + ((size_t)b * TT + frame) * FF);
        dst[tid] = src[tid];   // FF/4 = 128 float4 per frame
    }
}

// ---------------------------------------------------------------------------
extern "C" void kernel_launch(void* const* d_in, const int* in_sizes, int n_in,
                              void* d_out, int out_size)
{
    const float* x  = (const float*)d_in[0];
    const float* W1 = (const float*)d_in[1];
    const float* b1 = (const float*)d_in[2];
    const float* W2 = (const float*)d_in[3];
    const float* b2 = (const float*)d_in[4];
    const int*   kp = (const int*)d_in[5];
    float* out = (float*)d_out;

    cudaFuncSetAttribute(score_approx_kernel,
                         cudaFuncAttributeMaxDynamicSharedMemorySize, SM_TOTAL);
    cudaFuncSetAttribute(rescore_kernel,
                         cudaFuncAttributeMaxDynamicSharedMemorySize, R_TOTAL);

    wsplit_kernel<<<UU * FF / 256, 256>>>(W1);
    score_approx_kernel<<<NBLK, NTH, SM_TOTAL>>>(x, b1, W2, b2);
    topk_kernel<<<BB, 512>>>(kp);
    rescore_kernel<<<RBLK + ZBLK, 256, R_TOTAL>>>(x, b1, W2, b2, (float4*)out);
    select_kernel<<<BB, 128>>>(kp);
    scatter_kernel<<<dim3(BB, 16), 128>>>(x, out, kp);
}